// round 15
// baseline (speedup 1.0000x reference)
#include <cuda_runtime.h>
#include <math.h>

#define NNODES 8192
#define MAXDEG 128

// ---------------- scratch (no allocations allowed) ----------------
__device__ float g_Wh1 [NNODES * 200];
__device__ float g_Wh2 [2 * NNODES * 128];   // [Wh2a ; Wh2b]
__device__ float g_fbuf[6 * NNODES];         // fs1|fd1|fs2(2N)|fd2(2N)
__device__ int   g_col [2 * NNODES * MAXDEG];// [colA ; colT]
__device__ int   g_cnt [2 * NNODES];         // [cntA ; cntT]

// ---------------- helpers ----------------
__device__ __forceinline__ void add_edge(int i, int j, int* cnt, int* col) {
    int p = atomicAdd(&cnt[i], 1);
    if (p < MAXDEG) col[(size_t)i * MAXDEG + p] = j;
}

__device__ __forceinline__ float4 f4fma(float p, float4 w, float4 acc) {
    acc.x = fmaf(p, w.x, acc.x);
    acc.y = fmaf(p, w.y, acc.y);
    acc.z = fmaf(p, w.z, acc.z);
    acc.w = fmaf(p, w.w, acc.w);
    return acc;
}

// packed f32x2 helpers (sm_100+): two independent IEEE fp32 FMAs per instr
__device__ __forceinline__ unsigned long long pack2(float lo, float hi) {
    unsigned long long r;
    asm("mov.b64 %0, {%1, %2};" : "=l"(r) : "f"(lo), "f"(hi));
    return r;
}
__device__ __forceinline__ void unpack2(unsigned long long v, float& lo, float& hi) {
    asm("mov.b64 {%0, %1}, %2;" : "=f"(lo), "=f"(hi) : "l"(v));
}
__device__ __forceinline__ unsigned long long ffma2(unsigned long long a,
                                                    unsigned long long b,
                                                    unsigned long long c) {
    unsigned long long d;
    asm("fma.rn.f32x2 %0, %1, %2, %3;" : "=l"(d) : "l"(a), "l"(b), "l"(c));
    return d;
}

// ---------------- dense adjacency scan ----------------
// 32-bit indices, no bounds checks: total quads (2^24) = 16 x grid*block (2^20).
// Two unrolled batches of 8 loads (MLP=8). Bitwise-nonzero == (>0) since
// A_hat entries are exactly 0.0f / 1.0f.
__global__ void __launch_bounds__(256) scan_kernel(const uint4* __restrict__ adj,
                                                   int* __restrict__ cnt,
                                                   int* __restrict__ col) {
    int* cntT = cnt + NNODES;
    int* colT = col + (size_t)NNODES * MAXDEG;
    const unsigned stride = 1u << 20;                 // 4096 blocks x 256 threads
    unsigned base = blockIdx.x * 256u + threadIdx.x;  // < 2^20
#pragma unroll
    for (int half = 0; half < 2; half++) {
        uint4 val[8];
#pragma unroll
        for (int t = 0; t < 8; t++)
            val[t] = adj[base + (unsigned)(half * 8 + t) * stride];
#pragma unroll
        for (int t = 0; t < 8; t++) {
            uint4 v = val[t];
            if ((v.x | v.y | v.z | v.w) == 0u) continue;   // ~98% of quads
            unsigned idx = base + (unsigned)(half * 8 + t) * stride;
            int i  = (int)(idx >> 11);            // 2048 quads per row
            int j0 = (int)((idx & 2047u) * 4u);
            if (v.x) { add_edge(i, j0    , cnt, col); add_edge(j0    , i, cntT, colT); }
            if (v.y) { add_edge(i, j0 + 1, cnt, col); add_edge(j0 + 1, i, cntT, colT); }
            if (v.z) { add_edge(i, j0 + 2, cnt, col); add_edge(j0 + 2, i, cntT, colT); }
            if (v.w) { add_edge(i, j0 + 3, cnt, col); add_edge(j0 + 3, i, cntT, colT); }
        }
    }
}

// ---------------- double-buffered GEMM, 128x128 tile, 8x8 micro, f32x2 core ----------------
// C[M,Nc] = A'[M,K] @ B[K,Nc], where row r of A' is at
//   A + (r % 8192)*ldA + (r / 8192)*branchOff   (GAT concat layout support).
// BK=8, 256 threads. Epilogue: fs[r] += C_tile[r,:].a_src (atomic), same fd.
__global__ void __launch_bounds__(256) gemm_kernel(
    const float* __restrict__ A, int ldA, int branchOff,
    const float* __restrict__ B, float* __restrict__ C,
    int K, int Nc, int nColTiles,
    const float* __restrict__ av_src, const float* __restrict__ av_dst,
    float* __restrict__ fs, float* __restrict__ fd)
{
    __shared__ float As[2][8][128];
    __shared__ float Bs[2][8][128];

    int tid = threadIdx.x;
    int tx = tid & 15, ty = tid >> 4;
    int colTile = blockIdx.x % nColTiles;
    int rowTile = blockIdx.x / nColTiles;
    int rowBase = rowTile * 128;
    int colBase = colTile * 128;

    int aRow = tid >> 1;
    int aK4  = (tid & 1) * 4;
    int bK = tid >> 5;
    int bN = (tid & 31) * 4;
    int nIdx = colBase + bN;
    bool bFull = (nIdx + 3 < Nc);

    int r = rowBase + aRow;
    const float* arow = A + (size_t)(r & (NNODES - 1)) * ldA + (r >> 13) * branchOff;

    // packed accumulators: acc2[i][j] holds cols (2j, 2j+1) of micro-row i
    unsigned long long acc2[8][4];
#pragma unroll
    for (int i = 0; i < 8; i++)
#pragma unroll
        for (int j = 0; j < 4; j++) acc2[i][j] = 0ull;

    float4 aReg, bReg;
    aReg = *(const float4*)(arow + aK4);
    {
        const float* brow = B + (size_t)bK * Nc;
        if (bFull) bReg = *(const float4*)(brow + nIdx);
        else {
            bReg.x = (nIdx + 0 < Nc) ? brow[nIdx + 0] : 0.f;
            bReg.y = (nIdx + 1 < Nc) ? brow[nIdx + 1] : 0.f;
            bReg.z = (nIdx + 2 < Nc) ? brow[nIdx + 2] : 0.f;
            bReg.w = (nIdx + 3 < Nc) ? brow[nIdx + 3] : 0.f;
        }
    }
    As[0][aK4 + 0][aRow] = aReg.x;
    As[0][aK4 + 1][aRow] = aReg.y;
    As[0][aK4 + 2][aRow] = aReg.z;
    As[0][aK4 + 3][aRow] = aReg.w;
    *(float4*)&Bs[0][bK][bN] = bReg;
    __syncthreads();

    int cur = 0;
    for (int k0 = 8; k0 < K; k0 += 8) {
        aReg = *(const float4*)(arow + k0 + aK4);
        {
            const float* brow = B + (size_t)(k0 + bK) * Nc;
            if (bFull) bReg = *(const float4*)(brow + nIdx);
            else {
                bReg.x = (nIdx + 0 < Nc) ? brow[nIdx + 0] : 0.f;
                bReg.y = (nIdx + 1 < Nc) ? brow[nIdx + 1] : 0.f;
                bReg.z = (nIdx + 2 < Nc) ? brow[nIdx + 2] : 0.f;
                bReg.w = (nIdx + 3 < Nc) ? brow[nIdx + 3] : 0.f;
            }
        }
#pragma unroll
        for (int kk = 0; kk < 8; kk++) {
            float4 a0 = *(const float4*)&As[cur][kk][ty * 8];
            float4 a1 = *(const float4*)&As[cur][kk][ty * 8 + 4];
            float4 b0 = *(const float4*)&Bs[cur][kk][tx * 8];
            float4 b1 = *(const float4*)&Bs[cur][kk][tx * 8 + 4];
            unsigned long long b2[4] = {pack2(b0.x, b0.y), pack2(b0.z, b0.w),
                                        pack2(b1.x, b1.y), pack2(b1.z, b1.w)};
            float av[8] = {a0.x, a0.y, a0.z, a0.w, a1.x, a1.y, a1.z, a1.w};
#pragma unroll
            for (int i = 0; i < 8; i++) {
                unsigned long long a2 = pack2(av[i], av[i]);
#pragma unroll
                for (int j = 0; j < 4; j++) acc2[i][j] = ffma2(a2, b2[j], acc2[i][j]);
            }
        }
        int nxt = cur ^ 1;
        As[nxt][aK4 + 0][aRow] = aReg.x;
        As[nxt][aK4 + 1][aRow] = aReg.y;
        As[nxt][aK4 + 2][aRow] = aReg.z;
        As[nxt][aK4 + 3][aRow] = aReg.w;
        *(float4*)&Bs[nxt][bK][bN] = bReg;
        __syncthreads();
        cur = nxt;
    }
#pragma unroll
    for (int kk = 0; kk < 8; kk++) {
        float4 a0 = *(const float4*)&As[cur][kk][ty * 8];
        float4 a1 = *(const float4*)&As[cur][kk][ty * 8 + 4];
        float4 b0 = *(const float4*)&Bs[cur][kk][tx * 8];
        float4 b1 = *(const float4*)&Bs[cur][kk][tx * 8 + 4];
        unsigned long long b2[4] = {pack2(b0.x, b0.y), pack2(b0.z, b0.w),
                                    pack2(b1.x, b1.y), pack2(b1.z, b1.w)};
        float av[8] = {a0.x, a0.y, a0.z, a0.w, a1.x, a1.y, a1.z, a1.w};
#pragma unroll
        for (int i = 0; i < 8; i++) {
            unsigned long long a2 = pack2(av[i], av[i]);
#pragma unroll
            for (int j = 0; j < 4; j++) acc2[i][j] = ffma2(a2, b2[j], acc2[i][j]);
        }
    }

    // unpack, store C, fs/fd epilogue
    float as8[8], ad8[8];
#pragma unroll
    for (int j = 0; j < 8; j++) {
        int cc = colBase + tx * 8 + j;
        as8[j] = (cc < Nc) ? av_src[cc] : 0.f;
        ad8[j] = (cc < Nc) ? av_dst[cc] : 0.f;
    }
#pragma unroll
    for (int i = 0; i < 8; i++) {
        float c[8];
#pragma unroll
        for (int j = 0; j < 4; j++) unpack2(acc2[i][j], c[2 * j], c[2 * j + 1]);

        int rr = rowBase + ty * 8 + i;
        float* crow = C + (size_t)rr * Nc;
        int c0 = colBase + tx * 8;
        if (c0 + 7 < Nc) {
            float4 v0 = {c[0], c[1], c[2], c[3]};
            float4 v1 = {c[4], c[5], c[6], c[7]};
            *(float4*)(crow + c0)     = v0;
            *(float4*)(crow + c0 + 4) = v1;
        } else {
#pragma unroll
            for (int j = 0; j < 8; j++)
                if (c0 + j < Nc) crow[c0 + j] = c[j];
        }

        float ps = 0.f, pd = 0.f;
#pragma unroll
        for (int j = 0; j < 8; j++) {
            ps = fmaf(c[j], as8[j], ps);
            pd = fmaf(c[j], ad8[j], pd);
        }
#pragma unroll
        for (int o = 8; o > 0; o >>= 1) {
            ps += __shfl_xor_sync(0xffffffffu, ps, o);
            pd += __shfl_xor_sync(0xffffffffu, pd, o);
        }
        if (tx == 0) {
            atomicAdd(&fs[rr], ps);
            atomicAdd(&fd[rr], pd);
        }
    }
}

// ---------------- sparse GAT aggregation (4-edge unroll, 2 branches via blockIdx.y) ----------------
template <int F>
__global__ void __launch_bounds__(256) gat_agg_kernel(
    const int* __restrict__ colB, const int* __restrict__ cntB,
    const float* __restrict__ fsB, const float* __restrict__ fdB,
    const float* __restrict__ WhB,
    float* __restrict__ outB,
    int fsStride, long whStride, int outBranchOff, int outStride) {
    constexpr int F4 = F / 4;
    __shared__ float sp[8][MAXDEG];
    __shared__ int   sj[8][MAXDEG];

    int b = blockIdx.y;
    const int* col = colB + (size_t)b * NNODES * MAXDEG;
    const int* cnt = cntB + b * NNODES;
    const float* fs = fsB + (size_t)b * fsStride;
    const float* fd = fdB + (size_t)b * fsStride;
    const float* Wh = WhB + (size_t)b * whStride;
    float* outp = outB + b * outBranchOff;

    int w = threadIdx.x >> 5, lane = threadIdx.x & 31;
    int row = blockIdx.x * 8 + w;
    if (row >= NNODES) return;

    int c = min(cnt[row], MAXDEG);
    float4 A0 = {0,0,0,0}, A1 = {0,0,0,0}, A2 = {0,0,0,0}, A3 = {0,0,0,0};
    float4 B0 = {0,0,0,0}, B1 = {0,0,0,0}, B2 = {0,0,0,0}, B3 = {0,0,0,0};
    const bool seg2 = (F4 > 32) && (lane < F4 - 32);

    if (c > 0) {
        const int* cl = col + (size_t)row * MAXDEG;
        float fsr = fs[row];
        int jv[4];
        float sv[4];
#pragma unroll
        for (int t = 0; t < 4; t++) {
            int idx = lane + t * 32;
            if (idx < c) {
                int j = cl[idx];
                float z = fsr + __ldg(fd + j);
                sv[t] = z > 0.f ? z : 0.1f * z;   // leaky_relu alpha=0.1
                jv[t] = j;
            } else { sv[t] = -3.4e38f; jv[t] = 0; }
        }
        float m = fmaxf(fmaxf(sv[0], sv[1]), fmaxf(sv[2], sv[3]));
#pragma unroll
        for (int o = 16; o > 0; o >>= 1) m = fmaxf(m, __shfl_xor_sync(0xffffffffu, m, o));
        float ev[4];
        float zs = 0.f;
#pragma unroll
        for (int t = 0; t < 4; t++) {
            int idx = lane + t * 32;
            float e = (idx < c) ? expf(sv[t] - m) : 0.f;
            ev[t] = e; zs += e;
        }
#pragma unroll
        for (int o = 16; o > 0; o >>= 1) zs += __shfl_xor_sync(0xffffffffu, zs, o);
        float invZ = 1.f / zs;
#pragma unroll
        for (int t = 0; t < 4; t++) {
            int idx = lane + t * 32;
            if (idx < c) { sp[w][idx] = ev[t] * invZ; sj[w][idx] = jv[t]; }
        }
        __syncwarp();

        int idx = 0;
        for (; idx + 3 < c; idx += 4) {
            float p0 = sp[w][idx + 0]; int j0 = sj[w][idx + 0];
            float p1 = sp[w][idx + 1]; int j1 = sj[w][idx + 1];
            float p2 = sp[w][idx + 2]; int j2 = sj[w][idx + 2];
            float p3 = sp[w][idx + 3]; int j3 = sj[w][idx + 3];
            const float4* w0 = (const float4*)(Wh + (size_t)j0 * F);
            const float4* w1 = (const float4*)(Wh + (size_t)j1 * F);
            const float4* w2 = (const float4*)(Wh + (size_t)j2 * F);
            const float4* w3 = (const float4*)(Wh + (size_t)j3 * F);
            float4 v0 = __ldg(w0 + lane);
            float4 v1 = __ldg(w1 + lane);
            float4 v2 = __ldg(w2 + lane);
            float4 v3 = __ldg(w3 + lane);
            A0 = f4fma(p0, v0, A0);
            A1 = f4fma(p1, v1, A1);
            A2 = f4fma(p2, v2, A2);
            A3 = f4fma(p3, v3, A3);
            if (seg2) {
                float4 u0 = __ldg(w0 + 32 + lane);
                float4 u1 = __ldg(w1 + 32 + lane);
                float4 u2 = __ldg(w2 + 32 + lane);
                float4 u3 = __ldg(w3 + 32 + lane);
                B0 = f4fma(p0, u0, B0);
                B1 = f4fma(p1, u1, B1);
                B2 = f4fma(p2, u2, B2);
                B3 = f4fma(p3, u3, B3);
            }
        }
        for (; idx < c; idx++) {
            float p0 = sp[w][idx]; int j0 = sj[w][idx];
            const float4* w0 = (const float4*)(Wh + (size_t)j0 * F);
            A0 = f4fma(p0, __ldg(w0 + lane), A0);
            if (seg2) B0 = f4fma(p0, __ldg(w0 + 32 + lane), B0);
        }
    } else {
        // empty row: softmax over uniform -9e15 -> 1/N over ALL nodes
        for (int j = 0; j < NNODES; j++) {
            const float4* wr = (const float4*)(Wh + (size_t)j * F);
            A0 = f4fma(1.f, wr[lane], A0);
            if (seg2) B0 = f4fma(1.f, wr[32 + lane], B0);
        }
        float inv = 1.f / NNODES;
        A0.x *= inv; A0.y *= inv; A0.z *= inv; A0.w *= inv;
        B0.x *= inv; B0.y *= inv; B0.z *= inv; B0.w *= inv;
    }

    float4 s0 = {A0.x + A1.x + A2.x + A3.x, A0.y + A1.y + A2.y + A3.y,
                 A0.z + A1.z + A2.z + A3.z, A0.w + A1.w + A2.w + A3.w};
    float4 r0 = {fmaxf(s0.x, 0.f), fmaxf(s0.y, 0.f), fmaxf(s0.z, 0.f), fmaxf(s0.w, 0.f)};
    float* orow = outp + (size_t)row * outStride;
    *(float4*)(orow + 4 * lane) = r0;
    if (seg2) {
        float4 s1 = {B0.x + B1.x + B2.x + B3.x, B0.y + B1.y + B2.y + B3.y,
                     B0.z + B1.z + B2.z + B3.z, B0.w + B1.w + B2.w + B3.w};
        float4 r1 = {fmaxf(s1.x, 0.f), fmaxf(s1.y, 0.f), fmaxf(s1.z, 0.f), fmaxf(s1.w, 0.f)};
        *(float4*)(orow + 4 * lane + 128) = r1;
    }
}

// ---------------- launch ----------------
extern "C" void kernel_launch(void* const* d_in, const int* in_sizes, int n_in,
                              void* d_out, int out_size) {
    const float* A   = (const float*)d_in[0];
    const float* x   = (const float*)d_in[1];
    const float* W1  = (const float*)d_in[2];
    const float* a1s = (const float*)d_in[3];
    const float* a1d = (const float*)d_in[4];
    const float* W2  = (const float*)d_in[5];
    const float* a2s = (const float*)d_in[6];
    const float* a2d = (const float*)d_in[7];
    float* out = (float*)d_out;

    float *Wh1, *Wh2, *fbuf;
    int *col, *cnt;
    cudaGetSymbolAddress((void**)&Wh1,  g_Wh1);
    cudaGetSymbolAddress((void**)&Wh2,  g_Wh2);
    cudaGetSymbolAddress((void**)&fbuf, g_fbuf);
    cudaGetSymbolAddress((void**)&col,  g_col);
    cudaGetSymbolAddress((void**)&cnt,  g_cnt);

    float* fs1 = fbuf;
    float* fd1 = fbuf + NNODES;
    float* fs2 = fbuf + 2 * NNODES;   // 2*NNODES long
    float* fd2 = fbuf + 4 * NNODES;   // 2*NNODES long

    // Output layout: [ x (8192x256) | cat1 (8192x400) | cat2 (8192x256) ]
    float* part1 = out + (size_t)NNODES * 256;
    float* part2 = out + (size_t)NNODES * (256 + 400);

    cudaMemcpyAsync(out, x, (size_t)NNODES * 256 * sizeof(float),
                    cudaMemcpyDeviceToDevice);
    cudaMemsetAsync(cnt, 0, 2 * NNODES * sizeof(int));
    cudaMemsetAsync(fbuf, 0, 6 * NNODES * sizeof(float));

    // 1) dense adjacency scan -> edge lists of A and A^T
    scan_kernel<<<4096, 256>>>((const uint4*)A, cnt, col);

    // 2) layer-1 GEMM: Wh1 = x @ W1, with fs1/fd1 epilogue (64 row x 2 col tiles)
    gemm_kernel<<<128, 256>>>(x, 256, 0, W1, Wh1, 256, 200, 2,
                              a1s, a1d, fs1, fd1);

    // 3) layer-1 aggregation (both directed branches) -> part1 ([o1|o2] per row)
    gat_agg_kernel<200><<<dim3(1024, 2), 256>>>(
        col, cnt, fs1, fd1, Wh1, part1,
        /*fsStride=*/0, /*whStride=*/0, /*outBranchOff=*/200, /*outStride=*/400);

    // 4) layer-2 GEMM: Wh2 = [o1;o2] @ W2 (reads part1 directly, M=16384)
    gemm_kernel<<<128, 256>>>(part1, 400, 200, W2, Wh2, 200, 128, 1,
                              a2s, a2d, fs2, fd2);

    // 5) layer-2 aggregation -> part2
    gat_agg_kernel<128><<<dim3(1024, 2), 256>>>(
        col, cnt, fs2, fd2, Wh2, part2,
        /*fsStride=*/NNODES, /*whStride=*/(long)NNODES * 128, /*outBranchOff=*/128,
        /*outStride=*/256);
}

// round 16
// speedup vs baseline: 1.1165x; 1.1165x over previous
#include <cuda_runtime.h>
#include <math.h>

#define NNODES 8192
#define MAXDEG 128

// ---------------- scratch (no allocations allowed) ----------------
__device__ float g_Wh1 [NNODES * 200];
__device__ float g_Wh2 [2 * NNODES * 128];   // [Wh2a ; Wh2b]
__device__ float g_fbuf[6 * NNODES];         // fs1|fd1|fs2(2N)|fd2(2N)
__device__ int   g_col [2 * NNODES * MAXDEG];// [colA ; colT]
__device__ int   g_cnt [2 * NNODES];         // [cntA ; cntT]

// ---------------- helpers ----------------
__device__ __forceinline__ void add_edge(int i, int j, int* cnt, int* col) {
    int p = atomicAdd(&cnt[i], 1);
    if (p < MAXDEG) col[(size_t)i * MAXDEG + p] = j;
}

__device__ __forceinline__ float4 f4fma(float p, float4 w, float4 acc) {
    acc.x = fmaf(p, w.x, acc.x);
    acc.y = fmaf(p, w.y, acc.y);
    acc.z = fmaf(p, w.z, acc.z);
    acc.w = fmaf(p, w.w, acc.w);
    return acc;
}

// packed f32x2 helpers (sm_100+): two independent IEEE fp32 FMAs per instr
__device__ __forceinline__ unsigned long long pack2(float lo, float hi) {
    unsigned long long r;
    asm("mov.b64 %0, {%1, %2};" : "=l"(r) : "f"(lo), "f"(hi));
    return r;
}
__device__ __forceinline__ void unpack2(unsigned long long v, float& lo, float& hi) {
    asm("mov.b64 {%0, %1}, %2;" : "=f"(lo), "=f"(hi) : "l"(v));
}
__device__ __forceinline__ unsigned long long ffma2(unsigned long long a,
                                                    unsigned long long b,
                                                    unsigned long long c) {
    unsigned long long d;
    asm("fma.rn.f32x2 %0, %1, %2, %3;" : "=l"(d) : "l"(a), "l"(b), "l"(c));
    return d;
}

// ---------------- dense adjacency scan (contiguous 64KB block segments) ----------------
// Each block owns a contiguous 4096-quad (64KB) segment: perfect TLB/DRAM-row
// locality; warp loads are coalesced 512B lines; 4-deep MLP; zero-skip via
// bitwise OR (A_hat entries are exactly 0.0f / 1.0f).
__global__ void __launch_bounds__(256) scan_kernel(const uint4* __restrict__ adj,
                                                   int* __restrict__ cnt,
                                                   int* __restrict__ col) {
    int* cntT = cnt + NNODES;
    int* colT = col + (size_t)NNODES * MAXDEG;
    unsigned base = blockIdx.x * 4096u + threadIdx.x;   // quad index
#pragma unroll
    for (int g = 0; g < 4; g++) {
        uint4 val[4];
#pragma unroll
        for (int t = 0; t < 4; t++)
            val[t] = adj[base + (unsigned)(g * 4 + t) * 256u];
#pragma unroll
        for (int t = 0; t < 4; t++) {
            uint4 v = val[t];
            if ((v.x | v.y | v.z | v.w) == 0u) continue;   // ~98% of quads
            unsigned idx = base + (unsigned)(g * 4 + t) * 256u;
            int i  = (int)(idx >> 11);            // 2048 quads per row
            int j0 = (int)((idx & 2047u) * 4u);
            if (v.x) { add_edge(i, j0    , cnt, col); add_edge(j0    , i, cntT, colT); }
            if (v.y) { add_edge(i, j0 + 1, cnt, col); add_edge(j0 + 1, i, cntT, colT); }
            if (v.z) { add_edge(i, j0 + 2, cnt, col); add_edge(j0 + 2, i, cntT, colT); }
            if (v.w) { add_edge(i, j0 + 3, cnt, col); add_edge(j0 + 3, i, cntT, colT); }
        }
    }
}

// ---------------- double-buffered GEMM, 128x128 tile, 8x8 micro, f32x2 core ----------------
// C[M,Nc] = A'[M,K] @ B[K,Nc], where row r of A' is at
//   A + (r % 8192)*ldA + (r / 8192)*branchOff   (GAT concat layout support).
// BK=8, 256 threads. Epilogue: fs[r] += C_tile[r,:].a_src (atomic), same fd.
__global__ void __launch_bounds__(256) gemm_kernel(
    const float* __restrict__ A, int ldA, int branchOff,
    const float* __restrict__ B, float* __restrict__ C,
    int K, int Nc, int nColTiles,
    const float* __restrict__ av_src, const float* __restrict__ av_dst,
    float* __restrict__ fs, float* __restrict__ fd)
{
    __shared__ float As[2][8][128];
    __shared__ float Bs[2][8][128];

    int tid = threadIdx.x;
    int tx = tid & 15, ty = tid >> 4;
    int colTile = blockIdx.x % nColTiles;
    int rowTile = blockIdx.x / nColTiles;
    int rowBase = rowTile * 128;
    int colBase = colTile * 128;

    int aRow = tid >> 1;
    int aK4  = (tid & 1) * 4;
    int bK = tid >> 5;
    int bN = (tid & 31) * 4;
    int nIdx = colBase + bN;
    bool bFull = (nIdx + 3 < Nc);

    int r = rowBase + aRow;
    const float* arow = A + (size_t)(r & (NNODES - 1)) * ldA + (r >> 13) * branchOff;

    // packed accumulators: acc2[i][j] holds cols (2j, 2j+1) of micro-row i
    unsigned long long acc2[8][4];
#pragma unroll
    for (int i = 0; i < 8; i++)
#pragma unroll
        for (int j = 0; j < 4; j++) acc2[i][j] = 0ull;

    float4 aReg, bReg;
    aReg = *(const float4*)(arow + aK4);
    {
        const float* brow = B + (size_t)bK * Nc;
        if (bFull) bReg = *(const float4*)(brow + nIdx);
        else {
            bReg.x = (nIdx + 0 < Nc) ? brow[nIdx + 0] : 0.f;
            bReg.y = (nIdx + 1 < Nc) ? brow[nIdx + 1] : 0.f;
            bReg.z = (nIdx + 2 < Nc) ? brow[nIdx + 2] : 0.f;
            bReg.w = (nIdx + 3 < Nc) ? brow[nIdx + 3] : 0.f;
        }
    }
    As[0][aK4 + 0][aRow] = aReg.x;
    As[0][aK4 + 1][aRow] = aReg.y;
    As[0][aK4 + 2][aRow] = aReg.z;
    As[0][aK4 + 3][aRow] = aReg.w;
    *(float4*)&Bs[0][bK][bN] = bReg;
    __syncthreads();

    int cur = 0;
    for (int k0 = 8; k0 < K; k0 += 8) {
        aReg = *(const float4*)(arow + k0 + aK4);
        {
            const float* brow = B + (size_t)(k0 + bK) * Nc;
            if (bFull) bReg = *(const float4*)(brow + nIdx);
            else {
                bReg.x = (nIdx + 0 < Nc) ? brow[nIdx + 0] : 0.f;
                bReg.y = (nIdx + 1 < Nc) ? brow[nIdx + 1] : 0.f;
                bReg.z = (nIdx + 2 < Nc) ? brow[nIdx + 2] : 0.f;
                bReg.w = (nIdx + 3 < Nc) ? brow[nIdx + 3] : 0.f;
            }
        }
#pragma unroll
        for (int kk = 0; kk < 8; kk++) {
            float4 a0 = *(const float4*)&As[cur][kk][ty * 8];
            float4 a1 = *(const float4*)&As[cur][kk][ty * 8 + 4];
            float4 b0 = *(const float4*)&Bs[cur][kk][tx * 8];
            float4 b1 = *(const float4*)&Bs[cur][kk][tx * 8 + 4];
            unsigned long long b2[4] = {pack2(b0.x, b0.y), pack2(b0.z, b0.w),
                                        pack2(b1.x, b1.y), pack2(b1.z, b1.w)};
            float av[8] = {a0.x, a0.y, a0.z, a0.w, a1.x, a1.y, a1.z, a1.w};
#pragma unroll
            for (int i = 0; i < 8; i++) {
                unsigned long long a2 = pack2(av[i], av[i]);
#pragma unroll
                for (int j = 0; j < 4; j++) acc2[i][j] = ffma2(a2, b2[j], acc2[i][j]);
            }
        }
        int nxt = cur ^ 1;
        As[nxt][aK4 + 0][aRow] = aReg.x;
        As[nxt][aK4 + 1][aRow] = aReg.y;
        As[nxt][aK4 + 2][aRow] = aReg.z;
        As[nxt][aK4 + 3][aRow] = aReg.w;
        *(float4*)&Bs[nxt][bK][bN] = bReg;
        __syncthreads();
        cur = nxt;
    }
#pragma unroll
    for (int kk = 0; kk < 8; kk++) {
        float4 a0 = *(const float4*)&As[cur][kk][ty * 8];
        float4 a1 = *(const float4*)&As[cur][kk][ty * 8 + 4];
        float4 b0 = *(const float4*)&Bs[cur][kk][tx * 8];
        float4 b1 = *(const float4*)&Bs[cur][kk][tx * 8 + 4];
        unsigned long long b2[4] = {pack2(b0.x, b0.y), pack2(b0.z, b0.w),
                                    pack2(b1.x, b1.y), pack2(b1.z, b1.w)};
        float av[8] = {a0.x, a0.y, a0.z, a0.w, a1.x, a1.y, a1.z, a1.w};
#pragma unroll
        for (int i = 0; i < 8; i++) {
            unsigned long long a2 = pack2(av[i], av[i]);
#pragma unroll
            for (int j = 0; j < 4; j++) acc2[i][j] = ffma2(a2, b2[j], acc2[i][j]);
        }
    }

    // unpack, store C, fs/fd epilogue
    float as8[8], ad8[8];
#pragma unroll
    for (int j = 0; j < 8; j++) {
        int cc = colBase + tx * 8 + j;
        as8[j] = (cc < Nc) ? av_src[cc] : 0.f;
        ad8[j] = (cc < Nc) ? av_dst[cc] : 0.f;
    }
#pragma unroll
    for (int i = 0; i < 8; i++) {
        float c[8];
#pragma unroll
        for (int j = 0; j < 4; j++) unpack2(acc2[i][j], c[2 * j], c[2 * j + 1]);

        int rr = rowBase + ty * 8 + i;
        float* crow = C + (size_t)rr * Nc;
        int c0 = colBase + tx * 8;
        if (c0 + 7 < Nc) {
            float4 v0 = {c[0], c[1], c[2], c[3]};
            float4 v1 = {c[4], c[5], c[6], c[7]};
            *(float4*)(crow + c0)     = v0;
            *(float4*)(crow + c0 + 4) = v1;
        } else {
#pragma unroll
            for (int j = 0; j < 8; j++)
                if (c0 + j < Nc) crow[c0 + j] = c[j];
        }

        float ps = 0.f, pd = 0.f;
#pragma unroll
        for (int j = 0; j < 8; j++) {
            ps = fmaf(c[j], as8[j], ps);
            pd = fmaf(c[j], ad8[j], pd);
        }
#pragma unroll
        for (int o = 8; o > 0; o >>= 1) {
            ps += __shfl_xor_sync(0xffffffffu, ps, o);
            pd += __shfl_xor_sync(0xffffffffu, pd, o);
        }
        if (tx == 0) {
            atomicAdd(&fs[rr], ps);
            atomicAdd(&fd[rr], pd);
        }
    }
}

// ---------------- sparse GAT aggregation (4-edge unroll, 2 branches via blockIdx.y) ----------------
template <int F>
__global__ void __launch_bounds__(256) gat_agg_kernel(
    const int* __restrict__ colB, const int* __restrict__ cntB,
    const float* __restrict__ fsB, const float* __restrict__ fdB,
    const float* __restrict__ WhB,
    float* __restrict__ outB,
    int fsStride, long whStride, int outBranchOff, int outStride) {
    constexpr int F4 = F / 4;
    __shared__ float sp[8][MAXDEG];
    __shared__ int   sj[8][MAXDEG];

    int b = blockIdx.y;
    const int* col = colB + (size_t)b * NNODES * MAXDEG;
    const int* cnt = cntB + b * NNODES;
    const float* fs = fsB + (size_t)b * fsStride;
    const float* fd = fdB + (size_t)b * fsStride;
    const float* Wh = WhB + (size_t)b * whStride;
    float* outp = outB + b * outBranchOff;

    int w = threadIdx.x >> 5, lane = threadIdx.x & 31;
    int row = blockIdx.x * 8 + w;
    if (row >= NNODES) return;

    int c = min(cnt[row], MAXDEG);
    float4 A0 = {0,0,0,0}, A1 = {0,0,0,0}, A2 = {0,0,0,0}, A3 = {0,0,0,0};
    float4 B0 = {0,0,0,0}, B1 = {0,0,0,0}, B2 = {0,0,0,0}, B3 = {0,0,0,0};
    const bool seg2 = (F4 > 32) && (lane < F4 - 32);

    if (c > 0) {
        const int* cl = col + (size_t)row * MAXDEG;
        float fsr = fs[row];
        int jv[4];
        float sv[4];
#pragma unroll
        for (int t = 0; t < 4; t++) {
            int idx = lane + t * 32;
            if (idx < c) {
                int j = cl[idx];
                float z = fsr + __ldg(fd + j);
                sv[t] = z > 0.f ? z : 0.1f * z;   // leaky_relu alpha=0.1
                jv[t] = j;
            } else { sv[t] = -3.4e38f; jv[t] = 0; }
        }
        float m = fmaxf(fmaxf(sv[0], sv[1]), fmaxf(sv[2], sv[3]));
#pragma unroll
        for (int o = 16; o > 0; o >>= 1) m = fmaxf(m, __shfl_xor_sync(0xffffffffu, m, o));
        float ev[4];
        float zs = 0.f;
#pragma unroll
        for (int t = 0; t < 4; t++) {
            int idx = lane + t * 32;
            float e = (idx < c) ? expf(sv[t] - m) : 0.f;
            ev[t] = e; zs += e;
        }
#pragma unroll
        for (int o = 16; o > 0; o >>= 1) zs += __shfl_xor_sync(0xffffffffu, zs, o);
        float invZ = 1.f / zs;
#pragma unroll
        for (int t = 0; t < 4; t++) {
            int idx = lane + t * 32;
            if (idx < c) { sp[w][idx] = ev[t] * invZ; sj[w][idx] = jv[t]; }
        }
        __syncwarp();

        int idx = 0;
        for (; idx + 3 < c; idx += 4) {
            float p0 = sp[w][idx + 0]; int j0 = sj[w][idx + 0];
            float p1 = sp[w][idx + 1]; int j1 = sj[w][idx + 1];
            float p2 = sp[w][idx + 2]; int j2 = sj[w][idx + 2];
            float p3 = sp[w][idx + 3]; int j3 = sj[w][idx + 3];
            const float4* w0 = (const float4*)(Wh + (size_t)j0 * F);
            const float4* w1 = (const float4*)(Wh + (size_t)j1 * F);
            const float4* w2 = (const float4*)(Wh + (size_t)j2 * F);
            const float4* w3 = (const float4*)(Wh + (size_t)j3 * F);
            float4 v0 = __ldg(w0 + lane);
            float4 v1 = __ldg(w1 + lane);
            float4 v2 = __ldg(w2 + lane);
            float4 v3 = __ldg(w3 + lane);
            A0 = f4fma(p0, v0, A0);
            A1 = f4fma(p1, v1, A1);
            A2 = f4fma(p2, v2, A2);
            A3 = f4fma(p3, v3, A3);
            if (seg2) {
                float4 u0 = __ldg(w0 + 32 + lane);
                float4 u1 = __ldg(w1 + 32 + lane);
                float4 u2 = __ldg(w2 + 32 + lane);
                float4 u3 = __ldg(w3 + 32 + lane);
                B0 = f4fma(p0, u0, B0);
                B1 = f4fma(p1, u1, B1);
                B2 = f4fma(p2, u2, B2);
                B3 = f4fma(p3, u3, B3);
            }
        }
        for (; idx < c; idx++) {
            float p0 = sp[w][idx]; int j0 = sj[w][idx];
            const float4* w0 = (const float4*)(Wh + (size_t)j0 * F);
            A0 = f4fma(p0, __ldg(w0 + lane), A0);
            if (seg2) B0 = f4fma(p0, __ldg(w0 + 32 + lane), B0);
        }
    } else {
        // empty row: softmax over uniform -9e15 -> 1/N over ALL nodes
        for (int j = 0; j < NNODES; j++) {
            const float4* wr = (const float4*)(Wh + (size_t)j * F);
            A0 = f4fma(1.f, wr[lane], A0);
            if (seg2) B0 = f4fma(1.f, wr[32 + lane], B0);
        }
        float inv = 1.f / NNODES;
        A0.x *= inv; A0.y *= inv; A0.z *= inv; A0.w *= inv;
        B0.x *= inv; B0.y *= inv; B0.z *= inv; B0.w *= inv;
    }

    float4 s0 = {A0.x + A1.x + A2.x + A3.x, A0.y + A1.y + A2.y + A3.y,
                 A0.z + A1.z + A2.z + A3.z, A0.w + A1.w + A2.w + A3.w};
    float4 r0 = {fmaxf(s0.x, 0.f), fmaxf(s0.y, 0.f), fmaxf(s0.z, 0.f), fmaxf(s0.w, 0.f)};
    float* orow = outp + (size_t)row * outStride;
    *(float4*)(orow + 4 * lane) = r0;
    if (seg2) {
        float4 s1 = {B0.x + B1.x + B2.x + B3.x, B0.y + B1.y + B2.y + B3.y,
                     B0.z + B1.z + B2.z + B3.z, B0.w + B1.w + B2.w + B3.w};
        float4 r1 = {fmaxf(s1.x, 0.f), fmaxf(s1.y, 0.f), fmaxf(s1.z, 0.f), fmaxf(s1.w, 0.f)};
        *(float4*)(orow + 4 * lane + 128) = r1;
    }
}

// ---------------- launch ----------------
extern "C" void kernel_launch(void* const* d_in, const int* in_sizes, int n_in,
                              void* d_out, int out_size) {
    const float* A   = (const float*)d_in[0];
    const float* x   = (const float*)d_in[1];
    const float* W1  = (const float*)d_in[2];
    const float* a1s = (const float*)d_in[3];
    const float* a1d = (const float*)d_in[4];
    const float* W2  = (const float*)d_in[5];
    const float* a2s = (const float*)d_in[6];
    const float* a2d = (const float*)d_in[7];
    float* out = (float*)d_out;

    float *Wh1, *Wh2, *fbuf;
    int *col, *cnt;
    cudaGetSymbolAddress((void**)&Wh1,  g_Wh1);
    cudaGetSymbolAddress((void**)&Wh2,  g_Wh2);
    cudaGetSymbolAddress((void**)&fbuf, g_fbuf);
    cudaGetSymbolAddress((void**)&col,  g_col);
    cudaGetSymbolAddress((void**)&cnt,  g_cnt);

    float* fs1 = fbuf;
    float* fd1 = fbuf + NNODES;
    float* fs2 = fbuf + 2 * NNODES;   // 2*NNODES long
    float* fd2 = fbuf + 4 * NNODES;   // 2*NNODES long

    // Output layout: [ x (8192x256) | cat1 (8192x400) | cat2 (8192x256) ]
    float* part1 = out + (size_t)NNODES * 256;
    float* part2 = out + (size_t)NNODES * (256 + 400);

    cudaMemcpyAsync(out, x, (size_t)NNODES * 256 * sizeof(float),
                    cudaMemcpyDeviceToDevice);
    cudaMemsetAsync(cnt, 0, 2 * NNODES * sizeof(int));
    cudaMemsetAsync(fbuf, 0, 6 * NNODES * sizeof(float));

    // 1) dense adjacency scan -> edge lists of A and A^T
    scan_kernel<<<4096, 256>>>((const uint4*)A, cnt, col);

    // 2) layer-1 GEMM: Wh1 = x @ W1, with fs1/fd1 epilogue (64 row x 2 col tiles)
    gemm_kernel<<<128, 256>>>(x, 256, 0, W1, Wh1, 256, 200, 2,
                              a1s, a1d, fs1, fd1);

    // 3) layer-1 aggregation (both directed branches) -> part1 ([o1|o2] per row)
    gat_agg_kernel<200><<<dim3(1024, 2), 256>>>(
        col, cnt, fs1, fd1, Wh1, part1,
        /*fsStride=*/0, /*whStride=*/0, /*outBranchOff=*/200, /*outStride=*/400);

    // 4) layer-2 GEMM: Wh2 = [o1;o2] @ W2 (reads part1 directly, M=16384)
    gemm_kernel<<<128, 256>>>(part1, 400, 200, W2, Wh2, 200, 128, 1,
                              a2s, a2d, fs2, fd2);

    // 5) layer-2 aggregation -> part2
    gat_agg_kernel<128><<<dim3(1024, 2), 256>>>(
        col, cnt, fs2, fd2, Wh2, part2,
        /*fsStride=*/NNODES, /*whStride=*/(long)NNODES * 128, /*outBranchOff=*/128,
        /*outStride=*/256);
}